// round 3
// baseline (speedup 1.0000x reference)
#include <cuda_runtime.h>

#define BS    32
#define NTOK  512
#define DM    96
#define A2LEN 150
#define NTOT  (BS*NTOK)          // 16384
#define NDR   (BS*A2LEN)         // 4800 dense rows
#define YW    128                // compact y width (120 used + 8 pad)

// ---------------- scratch ----------------------------------------------------
__device__ float g_y  [NTOT * YW];        // compact qkv: [q32..72 | k32..72 | v32..72 | pad]
__device__ float g_yd [3 * NDR * 24];     // dense qkv planes: q,k,v (a2a rows only)
__device__ float g_sp [NTOT * 40];        // sparse attn out (b channels 32..72)
__device__ float g_dn [NDR * 24];         // dense attn out
__device__ int   g_inv[NTOK];             // token -> a2a index (or -1)
__device__ int   g_src[2 * NTOK * 32];    // transposed coo src: [i][r][t]

// ---------------- f32x2 helpers ----------------------------------------------
__device__ __forceinline__ void ffma2(unsigned long long& d,
                                      unsigned long long a,
                                      unsigned long long b) {
    asm("fma.rn.f32x2 %0, %1, %2, %0;" : "+l"(d) : "l"(a), "l"(b));
}
__device__ __forceinline__ unsigned long long bcast2(float v) {
    unsigned long long r; unsigned int u = __float_as_uint(v);
    asm("mov.b64 %0, {%1, %1};" : "=l"(r) : "r"(u));
    return r;
}
__device__ __forceinline__ unsigned long long addf2(unsigned long long a,
                                                    unsigned long long b) {
    unsigned long long r;
    asm("add.rn.f32x2 %0, %1, %2;" : "=l"(r) : "l"(a), "l"(b));
    return r;
}

// map compact output channel -> Wqv row
__device__ __forceinline__ int rowmap(int o) {
    if (o < 40)  return 32 + o;          // q ch 32..72
    if (o < 80)  return 88 + o;          // k ch 32..72 (rows 128..168)
    if (o < 120) return 144 + o;         // v ch 32..72 (rows 224..264)
    return 32;                           // pad (unused)
}

// ---------------- K_prep: transposed src + inverse a2a map --------------------
__global__ void k_prep(const int* __restrict__ coo0,
                       const int* __restrict__ coo1,
                       const int* __restrict__ a2a) {
    const int i = blockIdx.x;
    const int* coo = i ? coo1 : coo0;
    const int t = threadIdx.x;
    const int e = blockIdx.y * 512 + t;          // entry 0..16383
    int src = coo[e * 3 + 1];
    int tok = e >> 5, r = e & 31;
    g_src[i * 16384 + r * 512 + tok] = src;
    if (i == 0 && blockIdx.y == 0) {
        g_inv[t] = -1;
        __syncthreads();
        if (t < A2LEN) g_inv[a2a[t]] = t;
    }
}

// ---------------- K1: compact qkv GEMM (16384 x 128, K=96) --------------------
// grid 256: 64-token x 128-output tile; 256 threads; thread = 4 tok x 8 out.
__global__ void __launch_bounds__(256) k_qkv(const float* __restrict__ x,
                                             const float* __restrict__ W) {
    extern __shared__ __align__(16) float sm[];
    float* sX = sm;                  // 64*97
    float* sW = sm + 64*97;          // 96*130
    float* sB = sW + 96*130;         // 128
    const int t0 = blockIdx.x * 64;
    const int tid = threadIdx.x;

    for (int i = tid; i < 64*96; i += 256) {
        int t = i / 96, k = i - t*96;
        sX[t*97 + k] = x[(t0 + t)*96 + k];
    }
    for (int i = tid; i < 128*96; i += 256) {
        int o = i / 96, k = i - o*96;
        sW[k*130 + o] = W[rowmap(o)*97 + k];
    }
    if (tid < 128) sB[tid] = W[rowmap(tid)*97 + 96];
    __syncthreads();

    const int tokg = tid & 15;       // tokens: tokg + 16*t
    const int ob   = (tid >> 4) * 8; // 8 outputs = 4 f32x2 pairs
    unsigned long long acc[4][4];
#pragma unroll
    for (int j = 0; j < 4; j++) {
        unsigned long long bv = *(const unsigned long long*)&sB[ob + 2*j];
        acc[0][j] = bv; acc[1][j] = bv; acc[2][j] = bv; acc[3][j] = bv;
    }
#pragma unroll 4
    for (int k = 0; k < 96; k++) {
        unsigned long long w0 = *(const unsigned long long*)&sW[k*130 + ob];
        unsigned long long w1 = *(const unsigned long long*)&sW[k*130 + ob + 2];
        unsigned long long w2 = *(const unsigned long long*)&sW[k*130 + ob + 4];
        unsigned long long w3 = *(const unsigned long long*)&sW[k*130 + ob + 6];
#pragma unroll
        for (int t = 0; t < 4; t++) {
            unsigned long long xv = bcast2(sX[(tokg + 16*t)*97 + k]);
            ffma2(acc[t][0], xv, w0);
            ffma2(acc[t][1], xv, w1);
            ffma2(acc[t][2], xv, w2);
            ffma2(acc[t][3], xv, w3);
        }
    }
#pragma unroll
    for (int t = 0; t < 4; t++) {
        int tok = t0 + tokg + 16*t;
#pragma unroll
        for (int j = 0; j < 4; j++)
            *(unsigned long long*)&g_y[tok*YW + ob + 2*j] = acc[t][j];
    }
}

// ---------------- K2: dense-head qkv GEMM (4800 rows x 24, K=96, 3 planes) ----
__global__ void __launch_bounds__(192) k_qkvd(const float* __restrict__ x,
                                              const float* __restrict__ W,
                                              const int* __restrict__ a2a) {
    extern __shared__ __align__(16) float sm[];
    float* sX = sm;                  // 64*97
    float* sW = sm + 64*97;          // 96*26
    float* sB = sW + 96*26;          // 24
    int*   sRow = (int*)(sB + 24);   // 64
    const int r0 = blockIdx.x * 64;
    const int p  = blockIdx.y;       // plane: 0=q,1=k,2=v
    const int tid = threadIdx.x;

    if (tid < 64) {
        int r = r0 + tid;
        int b = r / A2LEN, d = r - b*A2LEN;
        sRow[tid] = b*NTOK + a2a[d];
    }
    for (int i = tid; i < 24*96; i += 192) {
        int o = i / 96, k = i - o*96;
        sW[k*26 + o] = W[(96*p + 72 + o)*97 + k];
    }
    if (tid < 24) sB[tid] = W[(96*p + 72 + tid)*97 + 96];
    __syncthreads();
    for (int i = tid; i < 64*96; i += 192) {
        int t = i / 96, k = i - t*96;
        sX[t*97 + k] = x[sRow[t]*96 + k];
    }
    __syncthreads();

    const int tokg = tid & 15;
    const int ob   = (tid >> 4) * 2;
    unsigned long long acc[4];
    {
        unsigned long long bv = *(const unsigned long long*)&sB[ob];
        acc[0] = bv; acc[1] = bv; acc[2] = bv; acc[3] = bv;
    }
#pragma unroll 8
    for (int k = 0; k < 96; k++) {
        unsigned long long w0 = *(const unsigned long long*)&sW[k*26 + ob];
#pragma unroll
        for (int t = 0; t < 4; t++)
            ffma2(acc[t], bcast2(sX[(tokg + 16*t)*97 + k]), w0);
    }
#pragma unroll
    for (int t = 0; t < 4; t++) {
        int r = r0 + tokg + 16*t;
        *(unsigned long long*)&g_yd[p*(NDR*24) + r*24 + ob] = acc[t];
    }
}

// ---------------- K3: sparse L1 attention ------------------------------------
// grid 512 = (b<<4)|(i<<3)|(h<<1)|half ; 256 threads; 1 token/thread.
// K/V in smem at stride 10 (src*10 mod 32 spreads bank starts).
__global__ void __launch_bounds__(256) k_sparse() {
    const int bx = blockIdx.x;
    const int b    = bx >> 4;
    const int i    = (bx >> 3) & 1;
    const int h    = (bx >> 1) & 3;
    const int half = bx & 1;
    const int qb = i*20 + h*5;       // compact channel base (q); k:+40, v:+80
    __shared__ __align__(16) float sK[NTOK*10];
    __shared__ __align__(16) float sV[NTOK*10];
    const int tid = threadIdx.x;
    for (int idx = tid; idx < NTOK*5; idx += 256) {
        int tok = idx / 5, w = idx - tok*5;
        const float* base = &g_y[(b*NTOK + tok)*YW];
        sK[tok*10 + w] = base[40 + qb + w];
        sV[tok*10 + w] = base[80 + qb + w];
    }
    __syncthreads();
    const float scale = 0.44721359549995793f;   // 1/sqrt(5)
    const int t = half*256 + tid;
    const int* srcp = &g_src[i * 16384 + t];
    const float* qp = &g_y[(b*NTOK + t)*YW + qb];
    float q0 = qp[0], q1 = qp[1], q2 = qp[2], q3 = qp[3], q4 = qp[4];
    float l = 0.f, a0 = 0.f, a1 = 0.f, a2 = 0.f, a3 = 0.f, a4 = 0.f;
#pragma unroll 8
    for (int r = 0; r < 32; r++) {
        int base = srcp[r*512] * 10;             // coalesced LDG
        float2 kA = *(const float2*)&sK[base];
        float2 kB = *(const float2*)&sK[base + 2];
        float  k4 = sK[base + 4];
        float s = fabsf(q0 - kA.x) + fabsf(q1 - kA.y) + fabsf(q2 - kB.x)
                + fabsf(q3 - kB.y) + fabsf(q4 - k4);
        float p = __expf(-s * scale);            // logits <= 0: safe, no max
        float2 vA = *(const float2*)&sV[base];
        float2 vB = *(const float2*)&sV[base + 2];
        float  v4 = sV[base + 4];
        l += p;
        a0 += p*vA.x; a1 += p*vA.y; a2 += p*vB.x; a3 += p*vB.y; a4 += p*v4;
    }
    float inv = 1.0f / l;
    float* op = &g_sp[(b*NTOK + t)*40 + i*20 + h*5];
    op[0] = a0*inv; op[1] = a1*inv; op[2] = a2*inv; op[3] = a3*inv; op[4] = a4*inv;
}

// ---------------- K4: dense a2a L1 attention ----------------------------------
// grid (32, 5); 512 threads = 4 schunk x 4 h x 32 d. shfl-reduce over schunk.
#define DST 26   // smem stride (even for float2 align; distinct banks per chunk)
__global__ void __launch_bounds__(512) k_dense() {
    const int b  = blockIdx.x;
    const int d0 = blockIdx.y * 32;
    __shared__ __align__(16) float sK[A2LEN*DST];
    __shared__ __align__(16) float sV[A2LEN*DST];
    const int tid = threadIdx.x;
    const int P = NDR * 24;
    for (int idx = tid; idx < A2LEN*24; idx += 512) {
        int s = idx / 24, c = idx - s*24;
        sK[s*DST + c] = g_yd[P   + b*A2LEN*24 + idx];
        sV[s*DST + c] = g_yd[2*P + b*A2LEN*24 + idx];
    }
    __syncthreads();
    const int sc = tid & 3;
    const int h  = (tid >> 2) & 3;
    const int dl = tid >> 4;
    const int d  = d0 + dl;
    const int dd = d < A2LEN ? d : A2LEN - 1;    // clamp; all lanes reach shfl
    const float* qp = &g_yd[(b*A2LEN + dd)*24 + h*6];
    float q[6];
#pragma unroll
    for (int w = 0; w < 6; w++) q[w] = qp[w];
    const float scale = 0.4082482904638631f;     // 1/sqrt(6)
    float l = 0.f;
    float acc[6] = {0.f,0.f,0.f,0.f,0.f,0.f};
    const int s0 = sc * 38;
    const int s1 = (s0 + 38 < A2LEN) ? s0 + 38 : A2LEN;
#pragma unroll 2
    for (int s = s0; s < s1; s++) {
        const float* kp = &sK[s*DST + h*6];
        float2 ka = *(const float2*)kp;
        float2 kb = *(const float2*)(kp + 2);
        float2 kc = *(const float2*)(kp + 4);
        float ds = fabsf(q[0]-ka.x) + fabsf(q[1]-ka.y) + fabsf(q[2]-kb.x)
                 + fabsf(q[3]-kb.y) + fabsf(q[4]-kc.x) + fabsf(q[5]-kc.y);
        float p = __expf(-ds * scale);
        l += p;
        const float* vp = &sV[s*DST + h*6];
        float2 va = *(const float2*)vp;
        float2 vb = *(const float2*)(vp + 2);
        float2 vc = *(const float2*)(vp + 4);
        acc[0] += p*va.x; acc[1] += p*va.y; acc[2] += p*vb.x;
        acc[3] += p*vb.y; acc[4] += p*vc.x; acc[5] += p*vc.y;
    }
    // reduce across the 4 schunk lanes (lane bits 0-1)
#pragma unroll
    for (int off = 1; off < 4; off <<= 1) {
        l += __shfl_xor_sync(0xffffffffu, l, off);
#pragma unroll
        for (int w = 0; w < 6; w++)
            acc[w] += __shfl_xor_sync(0xffffffffu, acc[w], off);
    }
    if (sc == 0 && d < A2LEN) {
        // zero-pad key: denominator only
        float ds = fabsf(q[0]) + fabsf(q[1]) + fabsf(q[2])
                 + fabsf(q[3]) + fabsf(q[4]) + fabsf(q[5]);
        l += __expf(-ds * scale);
        float inv = 1.0f / l;
        float* op = &g_dn[(b*A2LEN + d)*24 + h*6];
#pragma unroll
        for (int w = 0; w < 6; w++) op[w] = acc[w]*inv;
    }
}

// ---------------- K5: out = x + SiLU(b) @ Wf^T + bias --------------------------
__global__ void __launch_bounds__(256) k_final(const float* __restrict__ x,
                                               const float* __restrict__ Wf,
                                               float* __restrict__ out) {
    __shared__ __align__(16) float sY[64*65];   // [t][c] stride 65
    __shared__ __align__(16) float sW[64*98];   // [c][o] stride 98
    __shared__ __align__(16) float sB[96];
    const int t0 = blockIdx.x * 64;
    const int tid = threadIdx.x;

    for (int idx = tid; idx < 64*96; idx += 256) {
        int o = idx / 64, c = idx - o*64;
        sW[c*98 + o] = Wf[o*97 + 32 + c];
    }
    if (tid < 96) sB[tid] = Wf[tid*97 + 96];
    for (int idx = tid; idx < 64*64; idx += 256) {
        int c = idx >> 6, t = idx & 63;
        int tt = t0 + t;
        float v;
        if (c < 40) {
            v = g_sp[tt*40 + c];
        } else {
            int b = tt >> 9, tok = tt & 511;
            int d = g_inv[tok];
            v = (d >= 0) ? g_dn[(b*A2LEN + d)*24 + (c - 40)] : 0.f;
        }
        float sg = 1.0f / (1.0f + __expf(-1.702f * v));
        sY[t*65 + c] = v * sg;
    }
    __syncthreads();

    const int tb = (tid & 15) * 4;
    const int ob = (tid >> 4) * 6;
    unsigned long long acc[4][3];
#pragma unroll
    for (int j = 0; j < 3; j++) {
        unsigned long long bv = *(const unsigned long long*)&sB[ob + 2*j];
        acc[0][j] = bv; acc[1][j] = bv; acc[2][j] = bv; acc[3][j] = bv;
    }
#pragma unroll 8
    for (int k = 0; k < 64; k++) {
        unsigned long long w0 = *(const unsigned long long*)&sW[k*98 + ob];
        unsigned long long w1 = *(const unsigned long long*)&sW[k*98 + ob + 2];
        unsigned long long w2 = *(const unsigned long long*)&sW[k*98 + ob + 4];
#pragma unroll
        for (int t = 0; t < 4; t++) {
            unsigned long long yv = bcast2(sY[(tb + t)*65 + k]);
            ffma2(acc[t][0], yv, w0);
            ffma2(acc[t][1], yv, w1);
            ffma2(acc[t][2], yv, w2);
        }
    }
#pragma unroll
    for (int t = 0; t < 4; t++) {
        int tt = t0 + tb + t;
#pragma unroll
        for (int j = 0; j < 3; j++) {
            unsigned long long xv = *(const unsigned long long*)&x[tt*96 + ob + 2*j];
            *(unsigned long long*)&out[tt*96 + ob + 2*j] = addf2(acc[t][j], xv);
        }
    }
}

// ---------------- launch -------------------------------------------------------
extern "C" void kernel_launch(void* const* d_in, const int* in_sizes, int n_in,
                              void* d_out, int out_size) {
    const float* x    = (const float*)d_in[0];
    const float* wqv  = (const float*)d_in[1];
    const float* wf   = (const float*)d_in[2];
    const int*   coo0 = (const int*)d_in[3];
    const int*   coo1 = (const int*)d_in[4];
    const int*   a2a  = (const int*)d_in[5];
    float*       out  = (float*)d_out;
    (void)in_sizes; (void)n_in; (void)out_size;

    const int smem1 = (64*97 + 96*130 + 128) * sizeof(float);        // 75264
    const int smem2 = (64*97 + 96*26 + 24 + 64) * sizeof(float);     // 35168
    static int inited = 0;
    if (!inited) {
        cudaFuncSetAttribute(k_qkv,  cudaFuncAttributeMaxDynamicSharedMemorySize, smem1);
        cudaFuncSetAttribute(k_qkvd, cudaFuncAttributeMaxDynamicSharedMemorySize, smem2);
        inited = 1;
    }

    k_prep <<<dim3(2, 32), 512>>>(coo0, coo1, a2a);
    k_qkv  <<<256, 256, smem1>>>(x, wqv);
    k_qkvd <<<dim3(75, 3), 192, smem2>>>(x, wqv, a2a);
    k_sparse<<<512, 256>>>();
    k_dense <<<dim3(32, 5), 512>>>();
    k_final <<<256, 256>>>(x, wf, out);
}

// round 4
// speedup vs baseline: 1.0224x; 1.0224x over previous
#include <cuda_runtime.h>

#define BS    32
#define NTOK  512
#define DM    96
#define A2LEN 150
#define NTOT  (BS*NTOK)          // 16384
#define NDR   (BS*A2LEN)         // 4800 dense rows
#define YW    128                // compact y width (120 used + 8 pad)

// ---------------- scratch ----------------------------------------------------
__device__ float g_y  [NTOT * YW];        // compact qkv: [q32..72 | k32..72 | v32..72 | pad]
__device__ float g_yd [3 * NDR * 24];     // dense qkv planes: q,k,v (a2a rows only)
__device__ float g_sp [NTOT * 40];        // sparse attn out (b channels 32..72)
__device__ float g_dn [NDR * 24];         // dense attn out
__device__ int   g_inv[NTOK];             // token -> a2a index (or -1)
__device__ int   g_src[2 * NTOK * 32];    // transposed coo src: [i][r][t]

// ---------------- f32x2 helpers ----------------------------------------------
__device__ __forceinline__ void ffma2(unsigned long long& d,
                                      unsigned long long a,
                                      unsigned long long b) {
    asm("fma.rn.f32x2 %0, %1, %2, %0;" : "+l"(d) : "l"(a), "l"(b));
}
__device__ __forceinline__ unsigned long long bcast2(float v) {
    unsigned long long r; unsigned int u = __float_as_uint(v);
    asm("mov.b64 %0, {%1, %1};" : "=l"(r) : "r"(u));
    return r;
}
__device__ __forceinline__ unsigned long long addf2(unsigned long long a,
                                                    unsigned long long b) {
    unsigned long long r;
    asm("add.rn.f32x2 %0, %1, %2;" : "=l"(r) : "l"(a), "l"(b));
    return r;
}

// map compact output channel -> Wqv row
__device__ __forceinline__ int rowmap(int o) {
    if (o < 40)  return 32 + o;          // q ch 32..72
    if (o < 80)  return 88 + o;          // k ch 32..72 (rows 128..168)
    if (o < 120) return 144 + o;         // v ch 32..72 (rows 224..264)
    return 32;                           // pad (unused)
}

// ---------------- K_prep: transposed src + inverse a2a map --------------------
__global__ void k_prep(const int* __restrict__ coo0,
                       const int* __restrict__ coo1,
                       const int* __restrict__ a2a) {
    const int i = blockIdx.x;
    const int* coo = i ? coo1 : coo0;
    const int t = threadIdx.x;
    const int e = blockIdx.y * 512 + t;          // entry 0..16383
    int src = coo[e * 3 + 1];
    int tok = e >> 5, r = e & 31;
    g_src[i * 16384 + r * 512 + tok] = src;
    if (i == 0 && blockIdx.y == 0) {
        g_inv[t] = -1;
        __syncthreads();
        if (t < A2LEN) g_inv[a2a[t]] = t;
    }
}

// ---------------- K1: compact qkv GEMM (16384 x 128, K=96) --------------------
// grid (256, 2): 64-token x 64-output tile; 256 threads; thread = 4 tok x 4 out.
__global__ void __launch_bounds__(256) k_qkv(const float* __restrict__ x,
                                             const float* __restrict__ W) {
    extern __shared__ __align__(16) float sm[];
    float* sX = sm;                  // 64*97
    float* sW = sm + 64*97;          // 96*66
    float* sB = sW + 96*66;          // 64
    const int t0 = blockIdx.x * 64;
    const int o0 = blockIdx.y * 64;
    const int tid = threadIdx.x;

    for (int i = tid; i < 64*96; i += 256) {
        int t = i / 96, k = i - t*96;
        sX[t*97 + k] = x[(t0 + t)*96 + k];
    }
    for (int i = tid; i < 64*96; i += 256) {
        int o = i / 96, k = i - o*96;
        sW[k*66 + o] = W[rowmap(o0 + o)*97 + k];
    }
    if (tid < 64) sB[tid] = W[rowmap(o0 + tid)*97 + 96];
    __syncthreads();

    const int tokg = tid & 15;       // tokens: tokg + 16*t (conflict-free LDS)
    const int ob   = (tid >> 4) * 4; // 4 outputs = 2 f32x2 pairs
    unsigned long long acc[4][2];
#pragma unroll
    for (int j = 0; j < 2; j++) {
        unsigned long long bv = *(const unsigned long long*)&sB[ob + 2*j];
        acc[0][j] = bv; acc[1][j] = bv; acc[2][j] = bv; acc[3][j] = bv;
    }
#pragma unroll 8
    for (int k = 0; k < 96; k++) {
        unsigned long long w0 = *(const unsigned long long*)&sW[k*66 + ob];
        unsigned long long w1 = *(const unsigned long long*)&sW[k*66 + ob + 2];
#pragma unroll
        for (int t = 0; t < 4; t++) {
            unsigned long long xv = bcast2(sX[(tokg + 16*t)*97 + k]);
            ffma2(acc[t][0], xv, w0);
            ffma2(acc[t][1], xv, w1);
        }
    }
#pragma unroll
    for (int t = 0; t < 4; t++) {
        int tok = t0 + tokg + 16*t;
        *(unsigned long long*)&g_y[tok*YW + o0 + ob]     = acc[t][0];
        *(unsigned long long*)&g_y[tok*YW + o0 + ob + 2] = acc[t][1];
    }
}

// ---------------- K2: dense-head qkv GEMM (4800 rows x 24, K=96, 3 planes) ----
__global__ void __launch_bounds__(192) k_qkvd(const float* __restrict__ x,
                                              const float* __restrict__ W,
                                              const int* __restrict__ a2a) {
    extern __shared__ __align__(16) float sm[];
    float* sX = sm;                  // 64*97
    float* sW = sm + 64*97;          // 96*26
    float* sB = sW + 96*26;          // 24
    int*   sRow = (int*)(sB + 24);   // 64
    const int r0 = blockIdx.x * 64;
    const int p  = blockIdx.y;       // plane: 0=q,1=k,2=v
    const int tid = threadIdx.x;

    if (tid < 64) {
        int r = r0 + tid;
        int b = r / A2LEN, d = r - b*A2LEN;
        sRow[tid] = b*NTOK + a2a[d];
    }
    for (int i = tid; i < 24*96; i += 192) {
        int o = i / 96, k = i - o*96;
        sW[k*26 + o] = W[(96*p + 72 + o)*97 + k];
    }
    if (tid < 24) sB[tid] = W[(96*p + 72 + tid)*97 + 96];
    __syncthreads();
    for (int i = tid; i < 64*96; i += 192) {
        int t = i / 96, k = i - t*96;
        sX[t*97 + k] = x[sRow[t]*96 + k];
    }
    __syncthreads();

    const int tokg = tid & 15;
    const int ob   = (tid >> 4) * 2;
    unsigned long long acc[4];
    {
        unsigned long long bv = *(const unsigned long long*)&sB[ob];
        acc[0] = bv; acc[1] = bv; acc[2] = bv; acc[3] = bv;
    }
#pragma unroll 8
    for (int k = 0; k < 96; k++) {
        unsigned long long w0 = *(const unsigned long long*)&sW[k*26 + ob];
#pragma unroll
        for (int t = 0; t < 4; t++)
            ffma2(acc[t], bcast2(sX[(tokg + 16*t)*97 + k]), w0);
    }
#pragma unroll
    for (int t = 0; t < 4; t++) {
        int r = r0 + tokg + 16*t;
        *(unsigned long long*)&g_yd[p*(NDR*24) + r*24 + ob] = acc[t];
    }
}

// ---------------- K3: sparse L1 attention ------------------------------------
// grid 1024 = (b,i,h,quarter); 256 threads = 128 tokens x 2 r-chunks (16 each).
// K/V in smem at stride 10 (src*10 mod 32 spreads bank starts).
__global__ void __launch_bounds__(256) k_sparse() {
    const int bx = blockIdx.x;
    const int b    = bx >> 5;
    const int i    = (bx >> 4) & 1;
    const int h    = (bx >> 2) & 3;
    const int quar = bx & 3;
    const int qb = i*20 + h*5;       // compact channel base (q); k:+40, v:+80
    __shared__ __align__(16) float sK[NTOK*10];
    __shared__ __align__(16) float sV[NTOK*10];
    const int tid = threadIdx.x;
    for (int idx = tid; idx < NTOK*5; idx += 256) {
        int tok = idx / 5, w = idx - tok*5;
        const float* base = &g_y[(b*NTOK + tok)*YW];
        sK[tok*10 + w] = base[40 + qb + w];
        sV[tok*10 + w] = base[80 + qb + w];
    }
    __syncthreads();
    const float scale = 0.44721359549995793f;   // 1/sqrt(5)
    const int t  = quar*128 + (tid >> 1);
    const int rc = tid & 1;                     // r-chunk: 16 rounds each
    const int* srcp = &g_src[i * 16384 + rc*16*512 + t];
    const float* qp = &g_y[(b*NTOK + t)*YW + qb];
    float q0 = qp[0], q1 = qp[1], q2 = qp[2], q3 = qp[3], q4 = qp[4];
    float l = 0.f, a0 = 0.f, a1 = 0.f, a2 = 0.f, a3 = 0.f, a4 = 0.f;
#pragma unroll 8
    for (int r = 0; r < 16; r++) {
        int base = srcp[r*512] * 10;             // coalesced LDG
        float2 kA = *(const float2*)&sK[base];
        float2 kB = *(const float2*)&sK[base + 2];
        float  k4 = sK[base + 4];
        float s = fabsf(q0 - kA.x) + fabsf(q1 - kA.y) + fabsf(q2 - kB.x)
                + fabsf(q3 - kB.y) + fabsf(q4 - k4);
        float p = __expf(-s * scale);            // logits <= 0: safe, no max
        float2 vA = *(const float2*)&sV[base];
        float2 vB = *(const float2*)&sV[base + 2];
        float  v4 = sV[base + 4];
        l += p;
        a0 += p*vA.x; a1 += p*vA.y; a2 += p*vB.x; a3 += p*vB.y; a4 += p*v4;
    }
    // combine the two r-chunks (adjacent lanes)
    l  += __shfl_xor_sync(0xffffffffu, l,  1);
    a0 += __shfl_xor_sync(0xffffffffu, a0, 1);
    a1 += __shfl_xor_sync(0xffffffffu, a1, 1);
    a2 += __shfl_xor_sync(0xffffffffu, a2, 1);
    a3 += __shfl_xor_sync(0xffffffffu, a3, 1);
    a4 += __shfl_xor_sync(0xffffffffu, a4, 1);
    if (rc == 0) {
        float inv = 1.0f / l;
        float* op = &g_sp[(b*NTOK + t)*40 + i*20 + h*5];
        op[0] = a0*inv; op[1] = a1*inv; op[2] = a2*inv; op[3] = a3*inv; op[4] = a4*inv;
    }
}

// ---------------- K4: dense a2a L1 attention ----------------------------------
// grid (32, 5); 512 threads = 4 schunk x 4 h x 32 d. shfl-reduce over schunk.
#define DST 26   // smem stride (even for float2 align; distinct banks per chunk)
__global__ void __launch_bounds__(512) k_dense() {
    const int b  = blockIdx.x;
    const int d0 = blockIdx.y * 32;
    __shared__ __align__(16) float sK[A2LEN*DST];
    __shared__ __align__(16) float sV[A2LEN*DST];
    const int tid = threadIdx.x;
    const int P = NDR * 24;
    for (int idx = tid; idx < A2LEN*24; idx += 512) {
        int s = idx / 24, c = idx - s*24;
        sK[s*DST + c] = g_yd[P   + b*A2LEN*24 + idx];
        sV[s*DST + c] = g_yd[2*P + b*A2LEN*24 + idx];
    }
    __syncthreads();
    const int sc = tid & 3;
    const int h  = (tid >> 2) & 3;
    const int dl = tid >> 4;
    const int d  = d0 + dl;
    const int dd = d < A2LEN ? d : A2LEN - 1;    // clamp; all lanes reach shfl
    const float* qp = &g_yd[(b*A2LEN + dd)*24 + h*6];
    float q[6];
#pragma unroll
    for (int w = 0; w < 6; w++) q[w] = qp[w];
    const float scale = 0.4082482904638631f;     // 1/sqrt(6)
    float l = 0.f;
    float acc[6] = {0.f,0.f,0.f,0.f,0.f,0.f};
    const int s0 = sc * 38;
    const int s1 = (s0 + 38 < A2LEN) ? s0 + 38 : A2LEN;
#pragma unroll 2
    for (int s = s0; s < s1; s++) {
        const float* kp = &sK[s*DST + h*6];
        float2 ka = *(const float2*)kp;
        float2 kb = *(const float2*)(kp + 2);
        float2 kc = *(const float2*)(kp + 4);
        float ds = fabsf(q[0]-ka.x) + fabsf(q[1]-ka.y) + fabsf(q[2]-kb.x)
                 + fabsf(q[3]-kb.y) + fabsf(q[4]-kc.x) + fabsf(q[5]-kc.y);
        float p = __expf(-ds * scale);
        l += p;
        const float* vp = &sV[s*DST + h*6];
        float2 va = *(const float2*)vp;
        float2 vb = *(const float2*)(vp + 2);
        float2 vc = *(const float2*)(vp + 4);
        acc[0] += p*va.x; acc[1] += p*va.y; acc[2] += p*vb.x;
        acc[3] += p*vb.y; acc[4] += p*vc.x; acc[5] += p*vc.y;
    }
    // reduce across the 4 schunk lanes (lane bits 0-1)
#pragma unroll
    for (int off = 1; off < 4; off <<= 1) {
        l += __shfl_xor_sync(0xffffffffu, l, off);
#pragma unroll
        for (int w = 0; w < 6; w++)
            acc[w] += __shfl_xor_sync(0xffffffffu, acc[w], off);
    }
    if (sc == 0 && d < A2LEN) {
        // zero-pad key: denominator only
        float ds = fabsf(q[0]) + fabsf(q[1]) + fabsf(q[2])
                 + fabsf(q[3]) + fabsf(q[4]) + fabsf(q[5]);
        l += __expf(-ds * scale);
        float inv = 1.0f / l;
        float* op = &g_dn[(b*A2LEN + d)*24 + h*6];
#pragma unroll
        for (int w = 0; w < 6; w++) op[w] = acc[w]*inv;
    }
}

// ---------------- K5: out = x + SiLU(b) @ Wf^T + bias --------------------------
__global__ void __launch_bounds__(256) k_final(const float* __restrict__ x,
                                               const float* __restrict__ Wf,
                                               float* __restrict__ out) {
    __shared__ __align__(16) float sY[64*65];   // [t][c] stride 65
    __shared__ __align__(16) float sW[64*98];   // [c][o] stride 98
    __shared__ __align__(16) float sB[96];
    const int t0 = blockIdx.x * 64;
    const int tid = threadIdx.x;

    for (int idx = tid; idx < 64*96; idx += 256) {
        int o = idx / 64, c = idx - o*64;
        sW[c*98 + o] = Wf[o*97 + 32 + c];
    }
    if (tid < 96) sB[tid] = Wf[tid*97 + 96];
    for (int idx = tid; idx < 64*64; idx += 256) {
        int c = idx >> 6, t = idx & 63;
        int tt = t0 + t;
        float v;
        if (c < 40) {
            v = g_sp[tt*40 + c];
        } else {
            int b = tt >> 9, tok = tt & 511;
            int d = g_inv[tok];
            v = (d >= 0) ? g_dn[(b*A2LEN + d)*24 + (c - 40)] : 0.f;
        }
        float sg = 1.0f / (1.0f + __expf(-1.702f * v));
        sY[t*65 + c] = v * sg;
    }
    __syncthreads();

    const int tb = (tid & 15) * 4;
    const int ob = (tid >> 4) * 6;
    unsigned long long acc[4][3];
#pragma unroll
    for (int j = 0; j < 3; j++) {
        unsigned long long bv = *(const unsigned long long*)&sB[ob + 2*j];
        acc[0][j] = bv; acc[1][j] = bv; acc[2][j] = bv; acc[3][j] = bv;
    }
#pragma unroll 8
    for (int k = 0; k < 64; k++) {
        unsigned long long w0 = *(const unsigned long long*)&sW[k*98 + ob];
        unsigned long long w1 = *(const unsigned long long*)&sW[k*98 + ob + 2];
        unsigned long long w2 = *(const unsigned long long*)&sW[k*98 + ob + 4];
#pragma unroll
        for (int t = 0; t < 4; t++) {
            unsigned long long yv = bcast2(sY[(tb + t)*65 + k]);
            ffma2(acc[t][0], yv, w0);
            ffma2(acc[t][1], yv, w1);
            ffma2(acc[t][2], yv, w2);
        }
    }
#pragma unroll
    for (int t = 0; t < 4; t++) {
        int tt = t0 + tb + t;
#pragma unroll
        for (int j = 0; j < 3; j++) {
            unsigned long long xv = *(const unsigned long long*)&x[tt*96 + ob + 2*j];
            *(unsigned long long*)&out[tt*96 + ob + 2*j] = addf2(acc[t][j], xv);
        }
    }
}

// ---------------- launch -------------------------------------------------------
extern "C" void kernel_launch(void* const* d_in, const int* in_sizes, int n_in,
                              void* d_out, int out_size) {
    const float* x    = (const float*)d_in[0];
    const float* wqv  = (const float*)d_in[1];
    const float* wf   = (const float*)d_in[2];
    const int*   coo0 = (const int*)d_in[3];
    const int*   coo1 = (const int*)d_in[4];
    const int*   a2a  = (const int*)d_in[5];
    float*       out  = (float*)d_out;
    (void)in_sizes; (void)n_in; (void)out_size;

    const int smem1 = (64*97 + 96*66 + 64) * sizeof(float);          // 50432
    const int smem2 = (64*97 + 96*26 + 24 + 64) * sizeof(float);     // 35168
    static int inited = 0;
    if (!inited) {
        cudaFuncSetAttribute(k_qkv,  cudaFuncAttributeMaxDynamicSharedMemorySize, smem1);
        cudaFuncSetAttribute(k_qkvd, cudaFuncAttributeMaxDynamicSharedMemorySize, smem2);
        inited = 1;
    }

    k_prep <<<dim3(2, 32), 512>>>(coo0, coo1, a2a);
    k_qkv  <<<dim3(256, 2), 256, smem1>>>(x, wqv);
    k_qkvd <<<dim3(75, 3), 192, smem2>>>(x, wqv, a2a);
    k_sparse<<<1024, 256>>>();
    k_dense <<<dim3(32, 5), 512>>>();
    k_final <<<256, 256>>>(x, wf, out);
}

// round 5
// speedup vs baseline: 1.1909x; 1.1647x over previous
#include <cuda_runtime.h>

#define BS    32
#define NTOK  512
#define DM    96
#define A2LEN 150
#define NTOT  (BS*NTOK)          // 16384
#define NDR   (BS*A2LEN)         // 4800 dense rows
#define YW    128                // compact y width (120 used + 8 pad)

// ---------------- scratch ----------------------------------------------------
__device__ float g_y  [NTOT * YW];        // compact qkv: [q32..72 | k32..72 | v32..72 | pad]
__device__ float g_yd [3 * NDR * 24];     // dense qkv planes: q,k,v (a2a rows only)
__device__ float g_sp [NTOT * 40];        // sparse attn out (b channels 32..72)
__device__ float g_dn [NDR * 24];         // dense attn out
__device__ int   g_inv[NTOK];             // token -> a2a index (or -1)
__device__ int   g_src[2 * NTOK * 32];    // transposed coo src: [i][r][t]

// ---------------- f32x2 helpers ----------------------------------------------
__device__ __forceinline__ void ffma2(unsigned long long& d,
                                      unsigned long long a,
                                      unsigned long long b) {
    asm("fma.rn.f32x2 %0, %1, %2, %0;" : "+l"(d) : "l"(a), "l"(b));
}
__device__ __forceinline__ unsigned long long bcast2(float v) {
    unsigned long long r; unsigned int u = __float_as_uint(v);
    asm("mov.b64 %0, {%1, %1};" : "=l"(r) : "r"(u));
    return r;
}
__device__ __forceinline__ unsigned long long addf2(unsigned long long a,
                                                    unsigned long long b) {
    unsigned long long r;
    asm("add.rn.f32x2 %0, %1, %2;" : "=l"(r) : "l"(a), "l"(b));
    return r;
}

// map compact output channel -> Wqv row
__device__ __forceinline__ int rowmap(int o) {
    if (o < 40)  return 32 + o;          // q ch 32..72
    if (o < 80)  return 88 + o;          // k ch 32..72 (rows 128..168)
    if (o < 120) return 144 + o;         // v ch 32..72 (rows 224..264)
    return 32;                           // pad (unused)
}

// ---------------- K_prep: transposed src + inverse a2a map --------------------
__global__ void k_prep(const int* __restrict__ coo0,
                       const int* __restrict__ coo1,
                       const int* __restrict__ a2a) {
    const int i = blockIdx.x;
    const int* coo = i ? coo1 : coo0;
    const int t = threadIdx.x;
    const int e = blockIdx.y * 512 + t;          // entry 0..16383
    int src = coo[e * 3 + 1];
    int tok = e >> 5, r = e & 31;
    g_src[i * 16384 + r * 512 + tok] = src;
    if (i == 0 && blockIdx.y == 0) {
        g_inv[t] = -1;
        __syncthreads();
        if (t < A2LEN) g_inv[a2a[t]] = t;
    }
}

// ---------------- K1: compact qkv GEMM (16384 x 128, K=96) --------------------
// grid (256, 2): 64-token x 64-output tile; 256 threads; thread = 4 tok x 4 out.
__global__ void __launch_bounds__(256) k_qkv(const float* __restrict__ x,
                                             const float* __restrict__ W) {
    extern __shared__ __align__(16) float sm[];
    float* sX = sm;                  // 64*97
    float* sW = sm + 64*97;          // 96*66
    float* sB = sW + 96*66;          // 64
    const int t0 = blockIdx.x * 64;
    const int o0 = blockIdx.y * 64;
    const int tid = threadIdx.x;

    for (int i = tid; i < 64*96; i += 256) {
        int t = i / 96, k = i - t*96;
        sX[t*97 + k] = x[(t0 + t)*96 + k];
    }
    for (int i = tid; i < 64*96; i += 256) {
        int o = i / 96, k = i - o*96;
        sW[k*66 + o] = W[rowmap(o0 + o)*97 + k];
    }
    if (tid < 64) sB[tid] = W[rowmap(o0 + tid)*97 + 96];
    __syncthreads();

    const int tokg = tid & 15;       // tokens: tokg + 16*t (conflict-free LDS)
    const int ob   = (tid >> 4) * 4; // 4 outputs = 2 f32x2 pairs
    unsigned long long acc[4][2];
#pragma unroll
    for (int j = 0; j < 2; j++) {
        unsigned long long bv = *(const unsigned long long*)&sB[ob + 2*j];
        acc[0][j] = bv; acc[1][j] = bv; acc[2][j] = bv; acc[3][j] = bv;
    }
#pragma unroll 8
    for (int k = 0; k < 96; k++) {
        unsigned long long w0 = *(const unsigned long long*)&sW[k*66 + ob];
        unsigned long long w1 = *(const unsigned long long*)&sW[k*66 + ob + 2];
#pragma unroll
        for (int t = 0; t < 4; t++) {
            unsigned long long xv = bcast2(sX[(tokg + 16*t)*97 + k]);
            ffma2(acc[t][0], xv, w0);
            ffma2(acc[t][1], xv, w1);
        }
    }
#pragma unroll
    for (int t = 0; t < 4; t++) {
        int tok = t0 + tokg + 16*t;
        *(unsigned long long*)&g_y[tok*YW + o0 + ob]     = acc[t][0];
        *(unsigned long long*)&g_y[tok*YW + o0 + ob + 2] = acc[t][1];
    }
}

// ---------------- K2: dense-head qkv GEMM (4800 rows x 24, K=96, 3 planes) ----
__global__ void __launch_bounds__(192) k_qkvd(const float* __restrict__ x,
                                              const float* __restrict__ W,
                                              const int* __restrict__ a2a) {
    extern __shared__ __align__(16) float sm[];
    float* sX = sm;                  // 64*97
    float* sW = sm + 64*97;          // 96*26
    float* sB = sW + 96*26;          // 24
    int*   sRow = (int*)(sB + 24);   // 64
    const int r0 = blockIdx.x * 64;
    const int p  = blockIdx.y;       // plane: 0=q,1=k,2=v
    const int tid = threadIdx.x;

    if (tid < 64) {
        int r = r0 + tid;
        int b = r / A2LEN, d = r - b*A2LEN;
        sRow[tid] = b*NTOK + a2a[d];
    }
    for (int i = tid; i < 24*96; i += 192) {
        int o = i / 96, k = i - o*96;
        sW[k*26 + o] = W[(96*p + 72 + o)*97 + k];
    }
    if (tid < 24) sB[tid] = W[(96*p + 72 + tid)*97 + 96];
    __syncthreads();
    for (int i = tid; i < 64*96; i += 192) {
        int t = i / 96, k = i - t*96;
        sX[t*97 + k] = x[sRow[t]*96 + k];
    }
    __syncthreads();

    const int tokg = tid & 15;
    const int ob   = (tid >> 4) * 2;
    unsigned long long acc[4];
    {
        unsigned long long bv = *(const unsigned long long*)&sB[ob];
        acc[0] = bv; acc[1] = bv; acc[2] = bv; acc[3] = bv;
    }
#pragma unroll 8
    for (int k = 0; k < 96; k++) {
        unsigned long long w0 = *(const unsigned long long*)&sW[k*26 + ob];
#pragma unroll
        for (int t = 0; t < 4; t++)
            ffma2(acc[t], bcast2(sX[(tokg + 16*t)*97 + k]), w0);
    }
#pragma unroll
    for (int t = 0; t < 4; t++) {
        int r = r0 + tokg + 16*t;
        *(unsigned long long*)&g_yd[p*(NDR*24) + r*24 + ob] = acc[t];
    }
}

// ---------------- K3: sparse L1 attention (head-pair merged) ------------------
// grid 256 = (b<<3)|(i<<2)|quarter; 256 threads = 128 tokens x 2 head-pairs.
// smem layout: plane(p=K,V) x hp x [tok][12] (10 ch + 2 pad, 16B-aligned bases).
#define SPAD 12
#define SPL  (NTOK*SPAD)                 // 6144 floats per (plane,hp)
__global__ void __launch_bounds__(256) k_sparse() {
    extern __shared__ __align__(16) float sm[];   // 4 * 6144 floats = 96 KB
    const int bx = blockIdx.x;
    const int b    = bx >> 3;
    const int i    = (bx >> 2) & 1;
    const int quar = bx & 3;
    const int tid = threadIdx.x;

    // fill: K planes (p=0) then V (p=1); 10 ch per hp as 5 float2 per token
    for (int idx = tid; idx < 10240; idx += 256) {
        int p    = idx / 5120;
        int rem  = idx - p*5120;
        int hp   = rem / 2560;
        int rem2 = rem - hp*2560;
        int tok  = rem2 / 5;
        int c    = rem2 - tok*5;
        float2 v = *(const float2*)&g_y[(b*NTOK + tok)*YW + 40 + p*40 + i*20 + hp*10 + 2*c];
        *(float2*)&sm[(p*2 + hp)*SPL + tok*SPAD + 2*c] = v;
    }
    __syncthreads();

    const int t  = quar*128 + (tid >> 1);
    const int hp = tid & 1;
    const float* sK = sm + hp*SPL;
    const float* sV = sm + (2 + hp)*SPL;
    const float* qp = &g_y[(b*NTOK + t)*YW + i*20 + hp*10];
    float q[10];
#pragma unroll
    for (int w = 0; w < 10; w++) q[w] = qp[w];
    const int* srcp = &g_src[i * 16384 + t];
    const float scale = 0.44721359549995793f;   // 1/sqrt(5)
    float l0 = 0.f, l1 = 0.f;
    float acc[10] = {0.f,0.f,0.f,0.f,0.f,0.f,0.f,0.f,0.f,0.f};
#pragma unroll 4
    for (int r = 0; r < 32; r++) {
        int base = srcp[r*512] * SPAD;           // coalesced LDG
        float4 kA = *(const float4*)&sK[base];
        float4 kB = *(const float4*)&sK[base + 4];
        float2 kC = *(const float2*)&sK[base + 8];
        float s0 = fabsf(q[0]-kA.x) + fabsf(q[1]-kA.y) + fabsf(q[2]-kA.z)
                 + fabsf(q[3]-kA.w) + fabsf(q[4]-kB.x);
        float s1 = fabsf(q[5]-kB.y) + fabsf(q[6]-kB.z) + fabsf(q[7]-kB.w)
                 + fabsf(q[8]-kC.x) + fabsf(q[9]-kC.y);
        float p0 = __expf(-s0 * scale);          // logits <= 0: safe, no max
        float p1 = __expf(-s1 * scale);
        float4 vA = *(const float4*)&sV[base];
        float4 vB = *(const float4*)&sV[base + 4];
        float2 vC = *(const float2*)&sV[base + 8];
        l0 += p0; l1 += p1;
        acc[0] += p0*vA.x; acc[1] += p0*vA.y; acc[2] += p0*vA.z;
        acc[3] += p0*vA.w; acc[4] += p0*vB.x;
        acc[5] += p1*vB.y; acc[6] += p1*vB.z; acc[7] += p1*vB.w;
        acc[8] += p1*vC.x; acc[9] += p1*vC.y;
    }
    float inv0 = 1.0f / l0, inv1 = 1.0f / l1;
    float o_[10];
#pragma unroll
    for (int w = 0; w < 5; w++)  o_[w] = acc[w]*inv0;
#pragma unroll
    for (int w = 5; w < 10; w++) o_[w] = acc[w]*inv1;
    float* op = &g_sp[(b*NTOK + t)*40 + i*20 + hp*10];
#pragma unroll
    for (int w = 0; w < 5; w++)
        *(float2*)&op[2*w] = make_float2(o_[2*w], o_[2*w+1]);
}

// ---------------- K4: dense a2a L1 attention ----------------------------------
// grid (32, 5); 128 threads = 32 d x 4 h. Full s-loop per thread (R2 version).
__global__ void __launch_bounds__(128) k_dense() {
    const int b  = blockIdx.x;
    const int d0 = blockIdx.y * 32;
    __shared__ __align__(16) float sK[A2LEN*24];
    __shared__ __align__(16) float sV[A2LEN*24];
    const int tid = threadIdx.x;
    const int P = NDR * 24;
    for (int idx = tid; idx < A2LEN*24; idx += 128) {
        sK[idx] = g_yd[P   + b*A2LEN*24 + idx];
        sV[idx] = g_yd[2*P + b*A2LEN*24 + idx];
    }
    __syncthreads();
    const int dl = tid >> 2, h = tid & 3;
    const int d = d0 + dl;
    if (d >= A2LEN) return;
    const float* qp = &g_yd[(b*A2LEN + d)*24 + h*6];
    float q[6];
#pragma unroll
    for (int w = 0; w < 6; w++) q[w] = qp[w];
    const float scale = 0.4082482904638631f;    // 1/sqrt(6)
    float l = 0.f;
    float acc[6] = {0.f,0.f,0.f,0.f,0.f,0.f};
#pragma unroll 2
    for (int s = 0; s < A2LEN; s++) {
        const float* kp = &sK[s*24 + h*6];
        float2 ka = *(const float2*)kp;
        float2 kb = *(const float2*)(kp + 2);
        float2 kc = *(const float2*)(kp + 4);
        float ds = fabsf(q[0]-ka.x) + fabsf(q[1]-ka.y) + fabsf(q[2]-kb.x)
                 + fabsf(q[3]-kb.y) + fabsf(q[4]-kc.x) + fabsf(q[5]-kc.y);
        float p = __expf(-ds * scale);
        l += p;
        const float* vp = &sV[s*24 + h*6];
        float2 va = *(const float2*)vp;
        float2 vb = *(const float2*)(vp + 2);
        float2 vc = *(const float2*)(vp + 4);
        acc[0] += p*va.x; acc[1] += p*va.y; acc[2] += p*vb.x;
        acc[3] += p*vb.y; acc[4] += p*vc.x; acc[5] += p*vc.y;
    }
    {   // zero-pad key: denominator only
        float ds = fabsf(q[0]) + fabsf(q[1]) + fabsf(q[2])
                 + fabsf(q[3]) + fabsf(q[4]) + fabsf(q[5]);
        l += __expf(-ds * scale);
    }
    float inv = 1.0f / l;
    float* op = &g_dn[(b*A2LEN + d)*24 + h*6];
#pragma unroll
    for (int w = 0; w < 6; w++) op[w] = acc[w]*inv;
}

// ---------------- K5: out = x + SiLU(b) @ Wf^T + bias --------------------------
__global__ void __launch_bounds__(256) k_final(const float* __restrict__ x,
                                               const float* __restrict__ Wf,
                                               float* __restrict__ out) {
    __shared__ __align__(16) float sY[64*65];   // [t][c] stride 65
    __shared__ __align__(16) float sW[64*98];   // [c][o] stride 98
    __shared__ __align__(16) float sB[96];
    const int t0 = blockIdx.x * 64;
    const int tid = threadIdx.x;

    for (int idx = tid; idx < 64*96; idx += 256) {
        int o = idx / 64, c = idx - o*64;
        sW[c*98 + o] = Wf[o*97 + 32 + c];
    }
    if (tid < 96) sB[tid] = Wf[tid*97 + 96];
    for (int idx = tid; idx < 64*64; idx += 256) {
        int c = idx >> 6, t = idx & 63;
        int tt = t0 + t;
        float v;
        if (c < 40) {
            v = g_sp[tt*40 + c];
        } else {
            int b = tt >> 9, tok = tt & 511;
            int d = g_inv[tok];
            v = (d >= 0) ? g_dn[(b*A2LEN + d)*24 + (c - 40)] : 0.f;
        }
        float sg = 1.0f / (1.0f + __expf(-1.702f * v));
        sY[t*65 + c] = v * sg;
    }
    __syncthreads();

    const int tb = (tid & 15) * 4;
    const int ob = (tid >> 4) * 6;
    unsigned long long acc[4][3];
#pragma unroll
    for (int j = 0; j < 3; j++) {
        unsigned long long bv = *(const unsigned long long*)&sB[ob + 2*j];
        acc[0][j] = bv; acc[1][j] = bv; acc[2][j] = bv; acc[3][j] = bv;
    }
#pragma unroll 8
    for (int k = 0; k < 64; k++) {
        unsigned long long w0 = *(const unsigned long long*)&sW[k*98 + ob];
        unsigned long long w1 = *(const unsigned long long*)&sW[k*98 + ob + 2];
        unsigned long long w2 = *(const unsigned long long*)&sW[k*98 + ob + 4];
#pragma unroll
        for (int t = 0; t < 4; t++) {
            unsigned long long yv = bcast2(sY[(tb + t)*65 + k]);
            ffma2(acc[t][0], yv, w0);
            ffma2(acc[t][1], yv, w1);
            ffma2(acc[t][2], yv, w2);
        }
    }
#pragma unroll
    for (int t = 0; t < 4; t++) {
        int tt = t0 + tb + t;
#pragma unroll
        for (int j = 0; j < 3; j++) {
            unsigned long long xv = *(const unsigned long long*)&x[tt*96 + ob + 2*j];
            *(unsigned long long*)&out[tt*96 + ob + 2*j] = addf2(acc[t][j], xv);
        }
    }
}

// ---------------- launch -------------------------------------------------------
extern "C" void kernel_launch(void* const* d_in, const int* in_sizes, int n_in,
                              void* d_out, int out_size) {
    const float* x    = (const float*)d_in[0];
    const float* wqv  = (const float*)d_in[1];
    const float* wf   = (const float*)d_in[2];
    const int*   coo0 = (const int*)d_in[3];
    const int*   coo1 = (const int*)d_in[4];
    const int*   a2a  = (const int*)d_in[5];
    float*       out  = (float*)d_out;
    (void)in_sizes; (void)n_in; (void)out_size;

    const int smem1 = (64*97 + 96*66 + 64) * sizeof(float);          // 50432
    const int smem2 = (64*97 + 96*26 + 24 + 64) * sizeof(float);     // 35168
    const int smem3 = 4 * SPL * sizeof(float);                       // 98304
    static int inited = 0;
    if (!inited) {
        cudaFuncSetAttribute(k_qkv,   cudaFuncAttributeMaxDynamicSharedMemorySize, smem1);
        cudaFuncSetAttribute(k_qkvd,  cudaFuncAttributeMaxDynamicSharedMemorySize, smem2);
        cudaFuncSetAttribute(k_sparse,cudaFuncAttributeMaxDynamicSharedMemorySize, smem3);
        inited = 1;
    }

    k_prep <<<dim3(2, 32), 512>>>(coo0, coo1, a2a);
    k_qkv  <<<dim3(256, 2), 256, smem1>>>(x, wqv);
    k_qkvd <<<dim3(75, 3), 192, smem2>>>(x, wqv, a2a);
    k_sparse<<<256, 256, smem3>>>();
    k_dense <<<dim3(32, 5), 128>>>();
    k_final <<<256, 256>>>(x, wf, out);
}

// round 6
// speedup vs baseline: 1.4718x; 1.2359x over previous
#include <cuda_runtime.h>
#include <cuda_fp16.h>

#define BS    32
#define NTOK  512
#define A2LEN 150
#define NTOT  (BS*NTOK)          // 16384
#define NDR   (BS*A2LEN)         // 4800
#define YW    128                // compact y width (120 used + 8 pad)

// ---------------- scratch ----------------------------------------------------
__device__ float g_y  [NTOT * YW];
__device__ float g_yd [3 * NDR * 24];
__device__ float g_sp [NTOT * 40];
__device__ float g_dn [NDR * 24];
__device__ int   g_inv[NTOK];
__device__ int   g_src[2 * NTOK * 32];    // [i][r][t]

// ---------------- f32x2 helpers ----------------------------------------------
__device__ __forceinline__ void ffma2(unsigned long long& d,
                                      unsigned long long a,
                                      unsigned long long b) {
    asm("fma.rn.f32x2 %0, %1, %2, %0;" : "+l"(d) : "l"(a), "l"(b));
}
__device__ __forceinline__ unsigned long long bcast2(float v) {
    unsigned long long r; unsigned int u = __float_as_uint(v);
    asm("mov.b64 %0, {%1, %1};" : "=l"(r) : "r"(u));
    return r;
}
__device__ __forceinline__ unsigned long long addf2(unsigned long long a,
                                                    unsigned long long b) {
    unsigned long long r;
    asm("add.rn.f32x2 %0, %1, %2;" : "=l"(r) : "l"(a), "l"(b));
    return r;
}

__device__ __forceinline__ int rowmap(int o) {
    if (o < 40)  return 32 + o;
    if (o < 80)  return 88 + o;
    if (o < 120) return 144 + o;
    return 32;
}

// load 10 halves (8B-aligned) -> 10 floats
__device__ __forceinline__ void ld10h(const __half* p, float* f) {
    uint2 a = *(const uint2*)p;
    uint2 b = *(const uint2*)(p + 4);
    unsigned int c = *(const unsigned int*)(p + 8);
    float2 t;
    t = __half22float2(*(__half2*)&a.x); f[0]=t.x; f[1]=t.y;
    t = __half22float2(*(__half2*)&a.y); f[2]=t.x; f[3]=t.y;
    t = __half22float2(*(__half2*)&b.x); f[4]=t.x; f[5]=t.y;
    t = __half22float2(*(__half2*)&b.y); f[6]=t.x; f[7]=t.y;
    t = __half22float2(*(__half2*)&c);   f[8]=t.x; f[9]=t.y;
}

// =============== Kernel A: all GEMMs + prep (801 blocks, 256 thr) =============
// blocks [0,512): compact qkv tile 64tok x 64out
// blocks [512,737): dense-head qkv (225 blocks)
// blocks [737,801): coo transpose + inv map (64 blocks)
__global__ void __launch_bounds__(256) k_gemms(const float* __restrict__ x,
                                               const float* __restrict__ W,
                                               const int* __restrict__ coo0,
                                               const int* __restrict__ coo1,
                                               const int* __restrict__ a2a) {
    extern __shared__ __align__(16) float sm[];
    const int blk = blockIdx.x;
    const int tid = threadIdx.x;

    if (blk < 512) {
        float* sX = sm;                  // 64*97
        float* sW = sm + 64*97;          // 96*66
        float* sB = sW + 96*66;          // 64
        const int t0 = (blk >> 1) * 64;
        const int o0 = (blk & 1) * 64;
        for (int i = tid; i < 64*96; i += 256) {
            int t = i / 96, k = i - t*96;
            sX[t*97 + k] = x[(t0 + t)*96 + k];
        }
        for (int i = tid; i < 64*96; i += 256) {
            int o = i / 96, k = i - o*96;
            sW[k*66 + o] = W[rowmap(o0 + o)*97 + k];
        }
        if (tid < 64) sB[tid] = W[rowmap(o0 + tid)*97 + 96];
        __syncthreads();

        const int tokg = tid & 15;
        const int ob   = (tid >> 4) * 4;
        unsigned long long acc[4][2];
#pragma unroll
        for (int j = 0; j < 2; j++) {
            unsigned long long bv = *(const unsigned long long*)&sB[ob + 2*j];
            acc[0][j] = bv; acc[1][j] = bv; acc[2][j] = bv; acc[3][j] = bv;
        }
#pragma unroll 8
        for (int k = 0; k < 96; k++) {
            unsigned long long w0 = *(const unsigned long long*)&sW[k*66 + ob];
            unsigned long long w1 = *(const unsigned long long*)&sW[k*66 + ob + 2];
#pragma unroll
            for (int t = 0; t < 4; t++) {
                unsigned long long xv = bcast2(sX[(tokg + 16*t)*97 + k]);
                ffma2(acc[t][0], xv, w0);
                ffma2(acc[t][1], xv, w1);
            }
        }
#pragma unroll
        for (int t = 0; t < 4; t++) {
            int tok = t0 + tokg + 16*t;
            *(unsigned long long*)&g_y[tok*YW + o0 + ob]     = acc[t][0];
            *(unsigned long long*)&g_y[tok*YW + o0 + ob + 2] = acc[t][1];
        }
    } else if (blk < 737) {
        const int idx = blk - 512;               // 0..224
        const int r0 = (idx % 75) * 64;
        const int p  = idx / 75;                 // plane 0=q,1=k,2=v
        float* sX = sm;                  // 64*97
        float* sW = sm + 64*97;          // 96*26
        float* sB = sW + 96*26;          // 24
        int*   sRow = (int*)(sB + 24);   // 64

        if (tid < 64) {
            int r = r0 + tid;
            int b = r / A2LEN, d = r - b*A2LEN;
            sRow[tid] = b*NTOK + a2a[d];
        }
        for (int i = tid; i < 24*96; i += 256) {
            int o = i / 96, k = i - o*96;
            sW[k*26 + o] = W[(96*p + 72 + o)*97 + k];
        }
        if (tid < 24) sB[tid] = W[(96*p + 72 + tid)*97 + 96];
        __syncthreads();
        for (int i = tid; i < 64*96; i += 256) {
            int t = i / 96, k = i - t*96;
            sX[t*97 + k] = x[sRow[t]*96 + k];
        }
        __syncthreads();

        if (tid < 192) {
            const int tokg = tid & 15;
            const int ob   = (tid >> 4) * 2;
            unsigned long long acc[4];
            unsigned long long bv = *(const unsigned long long*)&sB[ob];
            acc[0] = bv; acc[1] = bv; acc[2] = bv; acc[3] = bv;
#pragma unroll 8
            for (int k = 0; k < 96; k++) {
                unsigned long long w0 = *(const unsigned long long*)&sW[k*26 + ob];
#pragma unroll
                for (int t = 0; t < 4; t++)
                    ffma2(acc[t], bcast2(sX[(tokg + 16*t)*97 + k]), w0);
            }
#pragma unroll
            for (int t = 0; t < 4; t++) {
                int r = r0 + tokg + 16*t;
                *(unsigned long long*)&g_yd[p*(NDR*24) + r*24 + ob] = acc[t];
            }
        }
    } else {
        const int pb = blk - 737;                // 0..63
#pragma unroll
        for (int j = 0; j < 2; j++) {
            int g = pb*512 + j*256 + tid;        // 0..32767
            int i = g >> 14;
            int e = g & 16383;
            const int* coo = i ? coo1 : coo0;
            int src = coo[e*3 + 1];
            int tok = e >> 5, r = e & 31;
            g_src[i*16384 + r*512 + tok] = src;
        }
        if (pb == 0) {
            g_inv[tid] = -1; g_inv[tid + 256] = -1;
            __syncthreads();
            if (tid < A2LEN) g_inv[a2a[tid]] = tid;
        }
    }
}

// =============== Kernel B: both attentions (352 blocks, 256 thr) ==============
// blocks [0,256): sparse (fp16 K/V, head-pair threads)
// blocks [256,352): dense (fp32, 64 d x 4 h per block)
#define SPLH (NTOK*12)           // halves per (plane,hp) = 6144 (12 KB)
__global__ void __launch_bounds__(256) k_attn() {
    extern __shared__ __align__(16) float smf[];
    const int blk = blockIdx.x;
    const int tid = threadIdx.x;

    if (blk < 256) {
        __half* hs = (__half*)smf;               // 4 * 6144 halves = 48 KB
        const int b    = blk >> 3;
        const int i    = (blk >> 2) & 1;
        const int quar = blk & 3;

        for (int idx = tid; idx < 10240; idx += 256) {
            int p    = idx / 5120;
            int rem  = idx - p*5120;
            int hp   = rem / 2560;
            int rem2 = rem - hp*2560;
            int tok  = rem2 / 5;
            int c    = rem2 - tok*5;
            float2 v = *(const float2*)&g_y[(b*NTOK + tok)*YW + 40 + p*40 + i*20 + hp*10 + 2*c];
            *(__half2*)&hs[(p*2 + hp)*SPLH + tok*12 + 2*c] = __float22half2_rn(v);
        }
        __syncthreads();

        const int t  = quar*128 + (tid >> 1);
        const int hp = tid & 1;
        const __half* sK = hs + hp*SPLH;
        const __half* sV = hs + (2 + hp)*SPLH;
        const float* qp = &g_y[(b*NTOK + t)*YW + i*20 + hp*10];
        float q[10];
#pragma unroll
        for (int w = 0; w < 10; w++) q[w] = qp[w];
        const int* srcp = &g_src[i*16384 + t];
        const float scale = 0.44721359549995793f;   // 1/sqrt(5)
        float l0 = 0.f, l1 = 0.f;
        float acc[10] = {0.f,0.f,0.f,0.f,0.f,0.f,0.f,0.f,0.f,0.f};
#pragma unroll 4
        for (int r = 0; r < 32; r++) {
            int base = srcp[r*512] * 12;
            float kf[10], vf[10];
            ld10h(&sK[base], kf);
            ld10h(&sV[base], vf);
            float s0 = fabsf(q[0]-kf[0]) + fabsf(q[1]-kf[1]) + fabsf(q[2]-kf[2])
                     + fabsf(q[3]-kf[3]) + fabsf(q[4]-kf[4]);
            float s1 = fabsf(q[5]-kf[5]) + fabsf(q[6]-kf[6]) + fabsf(q[7]-kf[7])
                     + fabsf(q[8]-kf[8]) + fabsf(q[9]-kf[9]);
            float p0 = __expf(-s0 * scale);          // logits <= 0: no max needed
            float p1 = __expf(-s1 * scale);
            l0 += p0; l1 += p1;
#pragma unroll
            for (int w = 0; w < 5; w++)  acc[w]   += p0*vf[w];
#pragma unroll
            for (int w = 5; w < 10; w++) acc[w]   += p1*vf[w];
        }
        float inv0 = 1.0f / l0, inv1 = 1.0f / l1;
        float o_[10];
#pragma unroll
        for (int w = 0; w < 5; w++)  o_[w] = acc[w]*inv0;
#pragma unroll
        for (int w = 5; w < 10; w++) o_[w] = acc[w]*inv1;
        float* op = &g_sp[(b*NTOK + t)*40 + i*20 + hp*10];
#pragma unroll
        for (int w = 0; w < 5; w++)
            *(float2*)&op[2*w] = make_float2(o_[2*w], o_[2*w+1]);
    } else {
        const int idx = blk - 256;               // 0..95
        const int b     = idx & 31;
        const int d0    = (idx >> 5) * 64;       // 0,64,128
        float* sK = smf;                         // 150*24
        float* sV = smf + A2LEN*24;
        const int P = NDR * 24;
        for (int j = tid; j < A2LEN*24; j += 256) {
            sK[j] = g_yd[P   + b*A2LEN*24 + j];
            sV[j] = g_yd[2*P + b*A2LEN*24 + j];
        }
        __syncthreads();
        const int dl = tid >> 2, h = tid & 3;
        const int d = d0 + dl;
        if (d >= A2LEN) return;
        const float* qp = &g_yd[(b*A2LEN + d)*24 + h*6];
        float q[6];
#pragma unroll
        for (int w = 0; w < 6; w++) q[w] = qp[w];
        const float scale = 0.4082482904638631f;    // 1/sqrt(6)
        float l = 0.f;
        float acc[6] = {0.f,0.f,0.f,0.f,0.f,0.f};
#pragma unroll 2
        for (int s = 0; s < A2LEN; s++) {
            const float* kp = &sK[s*24 + h*6];
            float2 ka = *(const float2*)kp;
            float2 kb = *(const float2*)(kp + 2);
            float2 kc = *(const float2*)(kp + 4);
            float ds = fabsf(q[0]-ka.x) + fabsf(q[1]-ka.y) + fabsf(q[2]-kb.x)
                     + fabsf(q[3]-kb.y) + fabsf(q[4]-kc.x) + fabsf(q[5]-kc.y);
            float p = __expf(-ds * scale);
            l += p;
            const float* vp = &sV[s*24 + h*6];
            float2 va = *(const float2*)vp;
            float2 vb = *(const float2*)(vp + 2);
            float2 vc = *(const float2*)(vp + 4);
            acc[0] += p*va.x; acc[1] += p*va.y; acc[2] += p*vb.x;
            acc[3] += p*vb.y; acc[4] += p*vc.x; acc[5] += p*vc.y;
        }
        {   // zero-pad key: denominator only
            float ds = fabsf(q[0]) + fabsf(q[1]) + fabsf(q[2])
                     + fabsf(q[3]) + fabsf(q[4]) + fabsf(q[5]);
            l += __expf(-ds * scale);
        }
        float inv = 1.0f / l;
        float* op = &g_dn[(b*A2LEN + d)*24 + h*6];
#pragma unroll
        for (int w = 0; w < 6; w++) op[w] = acc[w]*inv;
    }
}

// =============== Kernel C: out = x + SiLU(b) @ Wf^T + bias =====================
__global__ void __launch_bounds__(256) k_final(const float* __restrict__ x,
                                               const float* __restrict__ Wf,
                                               float* __restrict__ out) {
    __shared__ __align__(16) float sY[64*65];
    __shared__ __align__(16) float sW[64*98];
    __shared__ __align__(16) float sB[96];
    const int t0 = blockIdx.x * 64;
    const int tid = threadIdx.x;

    for (int idx = tid; idx < 64*96; idx += 256) {
        int o = idx / 64, c = idx - o*64;
        sW[c*98 + o] = Wf[o*97 + 32 + c];
    }
    if (tid < 96) sB[tid] = Wf[tid*97 + 96];
    for (int idx = tid; idx < 64*64; idx += 256) {
        int c = idx >> 6, t = idx & 63;
        int tt = t0 + t;
        float v;
        if (c < 40) {
            v = g_sp[tt*40 + c];
        } else {
            int b = tt >> 9, tok = tt & 511;
            int d = g_inv[tok];
            v = (d >= 0) ? g_dn[(b*A2LEN + d)*24 + (c - 40)] : 0.f;
        }
        float sg = 1.0f / (1.0f + __expf(-1.702f * v));
        sY[t*65 + c] = v * sg;
    }
    __syncthreads();

    const int tb = (tid & 15) * 4;
    const int ob = (tid >> 4) * 6;
    unsigned long long acc[4][3];
#pragma unroll
    for (int j = 0; j < 3; j++) {
        unsigned long long bv = *(const unsigned long long*)&sB[ob + 2*j];
        acc[0][j] = bv; acc[1][j] = bv; acc[2][j] = bv; acc[3][j] = bv;
    }
#pragma unroll 8
    for (int k = 0; k < 64; k++) {
        unsigned long long w0 = *(const unsigned long long*)&sW[k*98 + ob];
        unsigned long long w1 = *(const unsigned long long*)&sW[k*98 + ob + 2];
        unsigned long long w2 = *(const unsigned long long*)&sW[k*98 + ob + 4];
#pragma unroll
        for (int t = 0; t < 4; t++) {
            unsigned long long yv = bcast2(sY[(tb + t)*65 + k]);
            ffma2(acc[t][0], yv, w0);
            ffma2(acc[t][1], yv, w1);
            ffma2(acc[t][2], yv, w2);
        }
    }
#pragma unroll
    for (int t = 0; t < 4; t++) {
        int tt = t0 + tb + t;
#pragma unroll
        for (int j = 0; j < 3; j++) {
            unsigned long long xv = *(const unsigned long long*)&x[tt*96 + ob + 2*j];
            *(unsigned long long*)&out[tt*96 + ob + 2*j] = addf2(acc[t][j], xv);
        }
    }
}

// ---------------- launch -------------------------------------------------------
extern "C" void kernel_launch(void* const* d_in, const int* in_sizes, int n_in,
                              void* d_out, int out_size) {
    const float* x    = (const float*)d_in[0];
    const float* wqv  = (const float*)d_in[1];
    const float* wf   = (const float*)d_in[2];
    const int*   coo0 = (const int*)d_in[3];
    const int*   coo1 = (const int*)d_in[4];
    const int*   a2a  = (const int*)d_in[5];
    float*       out  = (float*)d_out;
    (void)in_sizes; (void)n_in; (void)out_size;

    const int smemA = (64*97 + 96*66 + 64) * sizeof(float);  // 50432
    const int smemB = 4 * SPLH * sizeof(__half);             // 49152
    static int inited = 0;
    if (!inited) {
        cudaFuncSetAttribute(k_gemms, cudaFuncAttributeMaxDynamicSharedMemorySize, smemA);
        cudaFuncSetAttribute(k_attn,  cudaFuncAttributeMaxDynamicSharedMemorySize, smemB);
        inited = 1;
    }

    k_gemms<<<801, 256, smemA>>>(x, wqv, coo0, coo1, a2a);
    k_attn <<<352, 256, smemB>>>();
    k_final<<<256, 256>>>(x, wf, out);
}